// round 2
// baseline (speedup 1.0000x reference)
#include <cuda_runtime.h>

#define M 8192
#define NT 25          // Taylor terms n = 0..24

// Scratch (allocation-free rule: __device__ globals)
__device__ float g_q[M], g_k[M], g_v[M];
__device__ float g_C[NT], g_D[NT];

// ---------------------------------------------------------------------------
// K1: fused triple GEMV  y = W @ x + b  for (Wq,bq)->g_q, (Wk,bk)->g_k, (Wv,bv)->g_v
// One warp per row, 8 rows per block, x staged in shared memory.
// grid = 3 * (8192/8) = 3072 blocks.
// ---------------------------------------------------------------------------
__global__ void __launch_bounds__(256) gemv3_kernel(
    const float* __restrict__ x,
    const float* __restrict__ Wq, const float* __restrict__ bq,
    const float* __restrict__ Wk, const float* __restrict__ bk,
    const float* __restrict__ Wv, const float* __restrict__ bv)
{
    __shared__ float4 sx[M / 4];          // 32 KB
    const int tid = threadIdx.x;

    const float4* x4 = reinterpret_cast<const float4*>(x);
#pragma unroll
    for (int i = 0; i < (M / 4) / 256; i++)
        sx[tid + i * 256] = x4[tid + i * 256];
    __syncthreads();

    const int mat  = blockIdx.x >> 10;    // 0:q 1:k 2:v
    const int blk  = blockIdx.x & 1023;
    const int warp = tid >> 5;
    const int lane = tid & 31;
    const int row  = blk * 8 + warp;

    const float* W;
    const float* b;
    float*       y;
    if (mat == 0)      { W = Wq; b = bq; y = g_q; }
    else if (mat == 1) { W = Wk; b = bk; y = g_k; }
    else               { W = Wv; b = bv; y = g_v; }

    const float4* Wr = reinterpret_cast<const float4*>(W + (size_t)row * M);

    float sum = 0.f;
#pragma unroll 8
    for (int c = lane; c < M / 4; c += 32) {
        float4 w  = Wr[c];
        float4 xx = sx[c];
        sum += w.x * xx.x + w.y * xx.y + w.z * xx.z + w.w * xx.w;
    }
#pragma unroll
    for (int o = 16; o; o >>= 1)
        sum += __shfl_xor_sync(0xffffffffu, sum, o);
    if (lane == 0)
        y[row] = sum + b[row];
}

// ---------------------------------------------------------------------------
// K2: moment accumulation (single block, 256 threads).
//   C_n = sum_j k_j^n / n!      D_n = sum_j k_j^n * v_j / n!
// Per-thread register accumulators, warp shuffle reduce, shared atomics.
// ---------------------------------------------------------------------------
__global__ void __launch_bounds__(256) moments_kernel()
{
    __shared__ float sC[NT], sD[NT];
    const int tid = threadIdx.x;
    if (tid < NT) { sC[tid] = 0.f; sD[tid] = 0.f; }
    __syncthreads();

    float C[NT], D[NT];
#pragma unroll
    for (int n = 0; n < NT; n++) { C[n] = 0.f; D[n] = 0.f; }

    for (int j = tid; j < M; j += 256) {
        const float k = g_k[j];
        const float v = g_v[j];
        float term = 1.f;                 // k^n / n!
#pragma unroll
        for (int n = 0; n < NT; n++) {
            C[n] += term;
            D[n] += term * v;
            term *= k * (1.0f / (float)(n + 1));
        }
    }

#pragma unroll
    for (int n = 0; n < NT; n++) {
        float c = C[n], d = D[n];
#pragma unroll
        for (int o = 16; o; o >>= 1) {
            c += __shfl_xor_sync(0xffffffffu, c, o);
            d += __shfl_xor_sync(0xffffffffu, d, o);
        }
        if ((tid & 31) == 0) {
            atomicAdd(&sC[n], c);
            atomicAdd(&sD[n], d);
        }
    }
    __syncthreads();
    if (tid < NT) { g_C[tid] = sC[tid]; g_D[tid] = sD[tid]; }
}

// ---------------------------------------------------------------------------
// K3: per-row softmax-weighted average via Horner evaluation of the two
// moment polynomials.  out[i] = S1(a_i) / S0(a_i),  a_i = q_i / 32.
// ---------------------------------------------------------------------------
__global__ void __launch_bounds__(256) finalize_kernel(float* __restrict__ out)
{
    const int i = blockIdx.x * 256 + threadIdx.x;
    const float a = g_q[i] * 0.03125f;    // 1/sqrt(1024) = 1/32

    float s0 = g_C[NT - 1];
    float s1 = g_D[NT - 1];
#pragma unroll
    for (int n = NT - 2; n >= 0; n--) {
        s0 = fmaf(s0, a, g_C[n]);
        s1 = fmaf(s1, a, g_D[n]);
    }
    out[i] = s1 / s0;
}

// ---------------------------------------------------------------------------
extern "C" void kernel_launch(void* const* d_in, const int* in_sizes, int n_in,
                              void* d_out, int out_size)
{
    const float* x  = (const float*)d_in[0];
    const float* Wq = (const float*)d_in[1];
    const float* bq = (const float*)d_in[2];
    const float* Wk = (const float*)d_in[3];
    const float* bk = (const float*)d_in[4];
    const float* Wv = (const float*)d_in[5];
    const float* bv = (const float*)d_in[6];

    gemv3_kernel<<<3072, 256>>>(x, Wq, bq, Wk, bk, Wv, bv);
    moments_kernel<<<1, 256>>>();
    finalize_kernel<<<M / 256, 256>>>((float*)d_out);
}

// round 3
// speedup vs baseline: 1.1517x; 1.1517x over previous
#include <cuda_runtime.h>

#define M 8192
#define NT 25          // Taylor terms n = 0..24

// Scratch (allocation-free rule: __device__ globals)
__device__ float g_q[M], g_k[M], g_v[M];
__device__ float g_C[NT], g_D[NT];

// ---------------------------------------------------------------------------
// K1: fused triple GEMV  y = W @ x + b  for (Wq,bq)->g_q, (Wk,bk)->g_k, (Wv,bv)->g_v
// One warp per row, 8 rows per block, x staged in shared memory.
// grid = 3 * (8192/8) = 3072 blocks.  (UNCHANGED from R1: 81% DRAM, 6.42 TB/s)
// Also zero-initializes the g_C/g_D accumulators (block 0) so the moments
// kernel can use global atomics; stream ordering guarantees happens-before.
// ---------------------------------------------------------------------------
__global__ void __launch_bounds__(256) gemv3_kernel(
    const float* __restrict__ x,
    const float* __restrict__ Wq, const float* __restrict__ bq,
    const float* __restrict__ Wk, const float* __restrict__ bk,
    const float* __restrict__ Wv, const float* __restrict__ bv)
{
    __shared__ float4 sx[M / 4];          // 32 KB
    const int tid = threadIdx.x;

    if (blockIdx.x == 0 && tid < NT) { g_C[tid] = 0.f; g_D[tid] = 0.f; }

    const float4* x4 = reinterpret_cast<const float4*>(x);
#pragma unroll
    for (int i = 0; i < (M / 4) / 256; i++)
        sx[tid + i * 256] = x4[tid + i * 256];
    __syncthreads();

    const int mat  = blockIdx.x >> 10;    // 0:q 1:k 2:v
    const int blk  = blockIdx.x & 1023;
    const int warp = tid >> 5;
    const int lane = tid & 31;
    const int row  = blk * 8 + warp;

    const float* W;
    const float* b;
    float*       y;
    if (mat == 0)      { W = Wq; b = bq; y = g_q; }
    else if (mat == 1) { W = Wk; b = bk; y = g_k; }
    else               { W = Wv; b = bv; y = g_v; }

    const float4* Wr = reinterpret_cast<const float4*>(W + (size_t)row * M);

    float sum = 0.f;
#pragma unroll 8
    for (int c = lane; c < M / 4; c += 32) {
        float4 w  = Wr[c];
        float4 xx = sx[c];
        sum += w.x * xx.x + w.y * xx.y + w.z * xx.z + w.w * xx.w;
    }
#pragma unroll
    for (int o = 16; o; o >>= 1)
        sum += __shfl_xor_sync(0xffffffffu, sum, o);
    if (lane == 0)
        y[row] = sum + b[row];
}

// ---------------------------------------------------------------------------
// K2: moment accumulation, 32 blocks x 256 threads (one j per thread).
//   C_n = sum_j k_j^n / n!      D_n = sum_j k_j^n * v_j / n!
// Warp shuffle reduce -> shared atomics (8-way) -> global atomics (32-way).
// g_C/g_D zeroed by gemv3 (stream-ordered before this kernel).
// ---------------------------------------------------------------------------
__global__ void __launch_bounds__(256) moments_kernel()
{
    __shared__ float sC[NT], sD[NT];
    const int tid = threadIdx.x;
    if (tid < NT) { sC[tid] = 0.f; sD[tid] = 0.f; }
    __syncthreads();

    const int j = blockIdx.x * 256 + tid;
    const float k = g_k[j];
    const float v = g_v[j];

    float C[NT], D[NT];
    float term = 1.f;                     // k^n / n!
#pragma unroll
    for (int n = 0; n < NT; n++) {
        C[n] = term;
        D[n] = term * v;
        term *= k * (1.0f / (float)(n + 1));
    }

#pragma unroll
    for (int n = 0; n < NT; n++) {
#pragma unroll
        for (int o = 16; o; o >>= 1) {
            C[n] += __shfl_xor_sync(0xffffffffu, C[n], o);
            D[n] += __shfl_xor_sync(0xffffffffu, D[n], o);
        }
    }
    if ((tid & 31) == 0) {
#pragma unroll
        for (int n = 0; n < NT; n++) {
            atomicAdd(&sC[n], C[n]);
            atomicAdd(&sD[n], D[n]);
        }
    }
    __syncthreads();
    if (tid < NT) {
        atomicAdd(&g_C[tid], sC[tid]);
        atomicAdd(&g_D[tid], sD[tid]);
    }
}

// ---------------------------------------------------------------------------
// K3: per-row softmax-weighted average via Horner evaluation of the two
// moment polynomials.  out[i] = S1(a_i) / S0(a_i),  a_i = q_i / 32.
// Moments staged in smem once per block.
// ---------------------------------------------------------------------------
__global__ void __launch_bounds__(256) finalize_kernel(float* __restrict__ out)
{
    __shared__ float sC[NT], sD[NT];
    const int tid = threadIdx.x;
    if (tid < NT) { sC[tid] = g_C[tid]; sD[tid] = g_D[tid]; }
    __syncthreads();

    const int i = blockIdx.x * 256 + tid;
    const float a = g_q[i] * 0.03125f;    // 1/sqrt(1024) = 1/32

    float s0 = sC[NT - 1];
    float s1 = sD[NT - 1];
#pragma unroll
    for (int n = NT - 2; n >= 0; n--) {
        s0 = fmaf(s0, a, sC[n]);
        s1 = fmaf(s1, a, sD[n]);
    }
    out[i] = s1 / s0;
}

// ---------------------------------------------------------------------------
extern "C" void kernel_launch(void* const* d_in, const int* in_sizes, int n_in,
                              void* d_out, int out_size)
{
    const float* x  = (const float*)d_in[0];
    const float* Wq = (const float*)d_in[1];
    const float* bq = (const float*)d_in[2];
    const float* Wk = (const float*)d_in[3];
    const float* bk = (const float*)d_in[4];
    const float* Wv = (const float*)d_in[5];
    const float* bv = (const float*)d_in[6];

    gemv3_kernel<<<3072, 256>>>(x, Wq, bq, Wk, bk, Wv, bv);
    moments_kernel<<<32, 256>>>();
    finalize_kernel<<<M / 256, 256>>>((float*)d_out);
}